// round 11
// baseline (speedup 1.0000x reference)
#include <cuda_runtime.h>
#include <math.h>

#define Bsz 1024
#define Ssz 350
#define Vsz 41
#define BT 8
#define NCTA 128
#define NTHR 256

typedef unsigned long long u64;

// ---------------- persistent device scratch ----------------
__device__ float4 g_A[49152];      // Whh0 e-pair packed: [kc][g][c2][j]
__device__ float4 g_B1rz[16384];   // Wih1 (r,z) pairs
__device__ float4 g_B1n[8192];     // Wih1 n rows
__device__ float4 g_B2rz[8192];    // Whh1 (r,z)
__device__ float4 g_B2n[4096];
__device__ float4 g_C1rz[2048];    // Wih2
__device__ float4 g_C1n[1024];
__device__ float4 g_C2rz[512];     // Whh2
__device__ float4 g_C2n[256];
__device__ float  g_WprojT[1312];  // [k][j]
__device__ float  g_G0x[41 * 768]; // [v][g][jm][e] pairs
__device__ float  g_Hinit[Bsz * 416];

// ---------------- helpers ----------------
__device__ __forceinline__ u64 fma2(u64 a, u64 b, u64 c) {
    u64 d; asm("fma.rn.f32x2 %0,%1,%2,%3;" : "=l"(d) : "l"(a), "l"(b), "l"(c)); return d;
}
__device__ __forceinline__ u64 add2(u64 a, u64 b) {
    u64 d; asm("add.rn.f32x2 %0,%1,%2;" : "=l"(d) : "l"(a), "l"(b)); return d;
}
__device__ __forceinline__ u64 pk2(float x, float y) {
    u64 d; asm("mov.b64 %0,{%1,%2};" : "=l"(d) : "f"(x), "f"(y)); return d;
}
__device__ __forceinline__ void up2(u64 a, float& x, float& y) {
    asm("mov.b64 {%0,%1}, %2;" : "=f"(x), "=f"(y) : "l"(a));
}
__device__ __forceinline__ float lo2(u64 a) { float x, y; up2(a, x, y); return x; }

__device__ __forceinline__ void cpa16(unsigned dst, const void* src) {
    asm volatile("cp.async.cg.shared.global [%0],[%1],16;" :: "r"(dst), "l"(src));
}
#define CP_COMMIT() asm volatile("cp.async.commit_group;" ::: "memory")
#define CP_WAIT(n)  asm volatile("cp.async.wait_group %0;" :: "n"(n) : "memory")

__device__ __forceinline__ float sigf(float x) {
    return __fdividef(1.0f, 1.0f + __expf(-x));
}
__device__ __forceinline__ float tanh_(float x) {
    float ax = fabsf(x);
    float e = __expf(-2.0f * ax);
    float t = __fdividef(1.0f - e, 1.0f + e);
    return copysignf(t, x);
}

// ---------------- fused prep kernel (identical to R2) ----------------
__global__ void k_prep(const float* __restrict__ latent, const float* __restrict__ W_emb,
                       const float* __restrict__ b_emb, const float* __restrict__ W_init,
                       const float* __restrict__ b_init, const float* __restrict__ Wih0,
                       const float* __restrict__ bih0, const float* __restrict__ Whh0,
                       const float* __restrict__ Wih1, const float* __restrict__ Whh1,
                       const float* __restrict__ Wih2, const float* __restrict__ Whh2,
                       const float* __restrict__ W_proj) {
    const int b = blockIdx.x, tid = threadIdx.x;
    if (b < 128) {
        __shared__ float lat[8 * 512];
        const int b0 = b * 8;
        for (int i = tid; i < 8 * 512; i += NTHR) lat[i] = latent[(size_t)b0 * 512 + i];
        __syncthreads();
        for (int c = tid; c < 416; c += NTHR) {
            float acc[8];
            float bi = b_init[c];
#pragma unroll
            for (int r = 0; r < 8; r++) acc[r] = bi;
            const float* w = W_init + (size_t)c * 512;
            for (int k = 0; k < 512; k += 4) {
                float4 wv = *(const float4*)(w + k);
#pragma unroll
                for (int r = 0; r < 8; r++) {
                    acc[r] += wv.x * lat[r * 512 + k];
                    acc[r] += wv.y * lat[r * 512 + k + 1];
                    acc[r] += wv.z * lat[r * 512 + k + 2];
                    acc[r] += wv.w * lat[r * 512 + k + 3];
                }
            }
#pragma unroll
            for (int r = 0; r < 8; r++) g_Hinit[(size_t)(b0 + r) * 416 + c] = acc[r];
        }
    } else if (b < 169) {
        const int v = b - 128;
        __shared__ float emb[512];
        for (int k = tid; k < 512; k += NTHR) emb[k] = W_emb[k * Vsz + v] + b_emb[k];
        __syncthreads();
        for (int j = tid; j < 768; j += NTHR) {
            float acc = bih0[j];
            const float* w = Wih0 + (size_t)j * 512;
            for (int k = 0; k < 512; k += 4) {
                float4 wv = *(const float4*)(w + k);
                acc += wv.x * emb[k] + wv.y * emb[k + 1] + wv.z * emb[k + 2] + wv.w * emb[k + 3];
            }
            int g = j >> 8, rem = j & 255, e = rem >> 7, jm = rem & 127;
            g_G0x[(((size_t)v * 3 + g) * 128 + jm) * 2 + e] = acc;
        }
    } else {
        const int TOTAL = 90184;
        for (int i = (b - 169) * NTHR + tid; i < TOTAL; i += 87 * NTHR) {
            if (i < 49152) {
                int kc = i / 768, rem = i % 768;
                int g = rem / 256, rem2 = rem % 256, c2 = rem2 >> 7, jj = rem2 & 127;
                int k = 4 * kc + 2 * c2, row0 = g * 256 + jj, row1 = row0 + 128;
                g_A[i] = make_float4(Whh0[row0 * 256 + k], Whh0[row1 * 256 + k],
                                     Whh0[row0 * 256 + k + 1], Whh0[row1 * 256 + k + 1]);
            } else if (i < 65536) {
                int t = i - 49152;
                int kc = t / 256, c2 = (t & 255) >> 7, jj = t & 127, k = 4 * kc + 2 * c2;
                g_B1rz[t] = make_float4(Wih1[jj * 256 + k], Wih1[(128 + jj) * 256 + k],
                                        Wih1[jj * 256 + k + 1], Wih1[(128 + jj) * 256 + k + 1]);
            } else if (i < 73728) {
                int t = i - 65536;
                int kc = t >> 7, jj = t & 127;
                g_B1n[t] = *(const float4*)&Wih1[(256 + jj) * 256 + 4 * kc];
            } else if (i < 81920) {
                int t = i - 73728;
                int kc = t / 256, c2 = (t & 255) >> 7, jj = t & 127, k = 4 * kc + 2 * c2;
                g_B2rz[t] = make_float4(Whh1[jj * 128 + k], Whh1[(128 + jj) * 128 + k],
                                        Whh1[jj * 128 + k + 1], Whh1[(128 + jj) * 128 + k + 1]);
            } else if (i < 86016) {
                int t = i - 81920;
                int kc = t >> 7, jj = t & 127;
                g_B2n[t] = *(const float4*)&Whh1[(256 + jj) * 128 + 4 * kc];
            } else if (i < 88064) {
                int t = i - 86016;
                int kc = t / 64, c2 = (t & 63) >> 5, jc = t & 31, k = 4 * kc + 2 * c2;
                g_C1rz[t] = make_float4(Wih2[jc * 128 + k], Wih2[(32 + jc) * 128 + k],
                                        Wih2[jc * 128 + k + 1], Wih2[(32 + jc) * 128 + k + 1]);
            } else if (i < 89088) {
                int t = i - 88064;
                int kc = t >> 5, jc = t & 31;
                g_C1n[t] = *(const float4*)&Wih2[(64 + jc) * 128 + 4 * kc];
            } else if (i < 89600) {
                int t = i - 89088;
                int kc = t / 64, c2 = (t & 63) >> 5, jc = t & 31, k = 4 * kc + 2 * c2;
                g_C2rz[t] = make_float4(Whh2[jc * 32 + k], Whh2[(32 + jc) * 32 + k],
                                        Whh2[jc * 32 + k + 1], Whh2[(32 + jc) * 32 + k + 1]);
            } else if (i < 89856) {
                int t = i - 89600;
                int kc = t >> 5, jc = t & 31;
                g_C2n[t] = *(const float4*)&Whh2[(64 + jc) * 32 + 4 * kc];
            } else {
                int t2 = i - 89856;
#pragma unroll
                for (int c = 0; c < 4; c++) {
                    int e = t2 * 4 + c;
                    if (e < 1312) {
                        int k = e / Vsz, j = e - k * Vsz;
                        g_WprojT[e] = W_proj[j * 32 + k];
                    }
                }
            }
        }
    }
}

// ---------------- dynamic smem layout (bytes) ----------------
#define OFF_H0   0        // u64[256*8]
#define OFF_H1   16384    // u64[128*8]
#define OFF_H2   24576    // u64[32*8]
#define OFF_LG   26624    // float[8*44] (pad to 1536)
#define OFF_TOK  28160    // int[350*8] (pad to 11264)
#define OFF_STA  39424    // A stage: 8 warps x 3 depth x 6 slots x 32 lanes x 16B = 73728
#define OFF_SB1  113152   // B1 stage: 8 x 3 x 3 x 32 x 16 = 36864
#define OFF_SB2  150016   // B2 stage: 36864
#define SM_TOTAL 186880

// ---------------- main persistent GRU kernel (R2 + cp.async weight staging) ----------------
__global__ __launch_bounds__(NTHR, 1)
void k_main(const int* __restrict__ tokens,
            const float* __restrict__ bhh0,
            const float* __restrict__ bih1, const float* __restrict__ bhh1,
            const float* __restrict__ bih2, const float* __restrict__ bhh2,
            const float* __restrict__ b_proj,
            float* __restrict__ out, float* __restrict__ pred) {
    extern __shared__ __align__(16) char smraw[];
    u64* h0d = (u64*)(smraw + OFF_H0);
    u64* h1d = (u64*)(smraw + OFF_H1);
    u64* h2d = (u64*)(smraw + OFF_H2);
    float* lg = (float*)(smraw + OFF_LG);
    int* toksAll = (int*)(smraw + OFF_TOK);

    const int tid = threadIdx.x;
    const int b0 = blockIdx.x * BT;
    const int warp = tid >> 5, lane = tid & 31;
    const int jj = tid & 127;
    const int r0 = (tid >> 7) * 4;
    const int jc = tid & 31;
    const int rowC = tid >> 5;

    // per-lane stage pointers (each lane consumes only what it stages)
    char* aBufG = smraw + OFF_STA + warp * 9216 + lane * 16;    // depth stride 3072, slot stride 512
    char* b1BufG = smraw + OFF_SB1 + warp * 4608 + lane * 16;   // depth stride 1536, slot stride 512
    char* b2BufG = smraw + OFF_SB2 + warp * 4608 + lane * 16;
    const unsigned aBufS = (unsigned)__cvta_generic_to_shared(aBufG);
    const unsigned b1BufS = (unsigned)__cvta_generic_to_shared(b1BufG);
    const unsigned b2BufS = (unsigned)__cvta_generic_to_shared(b2BufG);

    // tokens preload (SOS at step 0)
    for (int i = tid; i < Ssz * 8; i += NTHR) {
        int stt = i >> 3, row = i & 7;
        toksAll[i] = (stt == 0) ? 1 : tokens[(size_t)(b0 + row) * Ssz + stt];
    }

    // initial state -> dup smem
    for (int idx = tid; idx < BT * 416; idx += NTHR) {
        int row = idx / 416, c = idx - row * 416;
        float v = g_Hinit[(size_t)(b0 + row) * 416 + c];
        if (c < 256)      h0d[c * 8 + row] = pk2(v, v);
        else if (c < 384) h1d[(c - 256) * 8 + row] = pk2(v, v);
        else              h2d[(c - 384) * 8 + row] = pk2(v, v);
    }

    // register-resident packed biases (same as R2)
    const u64 bA_r = pk2(bhh0[jj], bhh0[128 + jj]);
    const u64 bA_z = pk2(bhh0[256 + jj], bhh0[384 + jj]);
    const u64 bA_n = pk2(bhh0[512 + jj], bhh0[640 + jj]);
    const u64 bB_rz = pk2(bih1[jj] + bhh1[jj], bih1[128 + jj] + bhh1[128 + jj]);
    const float b1in = bih1[256 + jj], b1hn = bhh1[256 + jj];
    const u64 bB_in = pk2(b1in, b1in);
    const u64 bB_hn = pk2(b1hn, b1hn);
    const u64 bC_rz = pk2(bih2[jc] + bhh2[jc], bih2[32 + jc] + bhh2[32 + jc]);
    const float b2in = bih2[64 + jc], b2hn = bhh2[64 + jc];
    const u64 bC_in = pk2(b2in, b2in);
    const u64 bC_hn = pk2(b2hn, b2hn);

    const u64* __restrict__ G0p = (const u64*)g_G0x;
    const float4* gsrcA = g_A + jj;
    const float4* gsrcB1rz = g_B1rz + jj;
    const float4* gsrcB1n = g_B1n + jj;
    const float4* gsrcB2rz = g_B2rz + jj;
    const float4* gsrcB2n = g_B2n + jj;

    __syncthreads();

    for (int st = 0; st < Ssz; st++) {
        const int* tokrow = toksAll + st * 8;

        // ======== Phase A: layer 0 (e-pair packed), cp.async staged weights ========
        u64 aR[4], aZ[4], aN[4], gIN[4];
#pragma unroll
        for (int r = 0; r < 4; r++) {
            const u64* g = G0p + (size_t)tokrow[r0 + r] * 384;
            aR[r] = add2(g[jj], bA_r);
            aZ[r] = add2(g[128 + jj], bA_z);
            gIN[r] = g[256 + jj];
            aN[r] = bA_n;
        }
        {
            // prologue: stage kc = 0,1,2
#pragma unroll
            for (int p = 0; p < 3; p++) {
                unsigned d = aBufS + p * 3072;
                const float4* s = gsrcA + p * 768;
                cpa16(d + 0, s);
                cpa16(d + 512, s + 128);
                cpa16(d + 1024, s + 256);
                cpa16(d + 1536, s + 384);
                cpa16(d + 2048, s + 512);
                cpa16(d + 2560, s + 640);
                CP_COMMIT();
            }
            for (int kc = 0; kc < 64; kc++) {
                if (kc < 62) { CP_WAIT(2); }
                else if (kc == 62) { CP_WAIT(1); }
                else { CP_WAIT(0); }
                const char* bp = aBufG + (kc % 3) * 3072;
                ulonglong2 wr0 = *(const ulonglong2*)(bp + 0);
                ulonglong2 wr1 = *(const ulonglong2*)(bp + 512);
                ulonglong2 wz0 = *(const ulonglong2*)(bp + 1024);
                ulonglong2 wz1 = *(const ulonglong2*)(bp + 1536);
                ulonglong2 wn0 = *(const ulonglong2*)(bp + 2048);
                ulonglong2 wn1 = *(const ulonglong2*)(bp + 2560);
                if (kc + 3 < 64) {
                    unsigned d = aBufS + ((kc + 3) % 3) * 3072;
                    const float4* s = gsrcA + (kc + 3) * 768;
                    cpa16(d + 0, s);
                    cpa16(d + 512, s + 128);
                    cpa16(d + 1024, s + 256);
                    cpa16(d + 1536, s + 384);
                    cpa16(d + 2048, s + 512);
                    cpa16(d + 2560, s + 640);
                    CP_COMMIT();
                }
                u64 wR[4] = {wr0.x, wr0.y, wr1.x, wr1.y};
                u64 wZ[4] = {wz0.x, wz0.y, wz1.x, wz1.y};
                u64 wN[4] = {wn0.x, wn0.y, wn1.x, wn1.y};
                u64 hv[4][4];
#pragma unroll
                for (int c = 0; c < 4; c++) {
                    ulonglong2 ha = *(const ulonglong2*)&h0d[(4 * kc + c) * 8 + r0];
                    ulonglong2 hb = *(const ulonglong2*)&h0d[(4 * kc + c) * 8 + r0 + 2];
                    hv[c][0] = ha.x; hv[c][1] = ha.y; hv[c][2] = hb.x; hv[c][3] = hb.y;
                }
#pragma unroll
                for (int c = 0; c < 4; c++)
#pragma unroll
                    for (int r = 0; r < 4; r++) {
                        aR[r] = fma2(wR[c], hv[c][r], aR[r]);
                        aZ[r] = fma2(wZ[c], hv[c][r], aZ[r]);
                        aN[r] = fma2(wN[c], hv[c][r], aN[r]);
                    }
            }
        }
        __syncthreads();
#pragma unroll
        for (int r = 0; r < 4; r++) {
            float r0e, r1e, z0e, z1e, n0e, n1e, i0e, i1e;
            up2(aR[r], r0e, r1e); up2(aZ[r], z0e, z1e);
            up2(aN[r], n0e, n1e); up2(gIN[r], i0e, i1e);
            float hold0 = lo2(h0d[jj * 8 + r0 + r]);
            float hold1 = lo2(h0d[(128 + jj) * 8 + r0 + r]);
            float rg0 = sigf(r0e), rg1 = sigf(r1e);
            float zg0 = sigf(z0e), zg1 = sigf(z1e);
            float ng0 = tanh_(i0e + rg0 * n0e), ng1 = tanh_(i1e + rg1 * n1e);
            float v0 = (1.0f - zg0) * ng0 + zg0 * hold0;
            float v1 = (1.0f - zg1) * ng1 + zg1 * hold1;
            h0d[jj * 8 + r0 + r] = pk2(v0, v0);
            h0d[(128 + jj) * 8 + r0 + r] = pk2(v1, v1);
        }
        __syncthreads();

        // ======== Phase B: layer 1 (gate-pair packed), staged ========
        u64 rz[4], iN[4], hN[4];
#pragma unroll
        for (int r = 0; r < 4; r++) { rz[r] = bB_rz; iN[r] = bB_in; hN[r] = bB_hn; }
        {
#pragma unroll
            for (int p = 0; p < 3; p++) {
                unsigned d = b1BufS + p * 1536;
                cpa16(d + 0, gsrcB1rz + p * 256);
                cpa16(d + 512, gsrcB1rz + p * 256 + 128);
                cpa16(d + 1024, gsrcB1n + p * 128);
                CP_COMMIT();
            }
            for (int kc = 0; kc < 64; kc++) {
                if (kc < 62) { CP_WAIT(2); }
                else if (kc == 62) { CP_WAIT(1); }
                else { CP_WAIT(0); }
                const char* bp = b1BufG + (kc % 3) * 1536;
                ulonglong2 w01 = *(const ulonglong2*)(bp + 0);
                ulonglong2 w23 = *(const ulonglong2*)(bp + 512);
                float4 wn4 = *(const float4*)(bp + 1024);
                if (kc + 3 < 64) {
                    unsigned d = b1BufS + ((kc + 3) % 3) * 1536;
                    cpa16(d + 0, gsrcB1rz + (kc + 3) * 256);
                    cpa16(d + 512, gsrcB1rz + (kc + 3) * 256 + 128);
                    cpa16(d + 1024, gsrcB1n + (kc + 3) * 128);
                    CP_COMMIT();
                }
                u64 wrz[4] = {w01.x, w01.y, w23.x, w23.y};
                u64 wnd[4] = {pk2(wn4.x, wn4.x), pk2(wn4.y, wn4.y),
                              pk2(wn4.z, wn4.z), pk2(wn4.w, wn4.w)};
                u64 hv[4][4];
#pragma unroll
                for (int c = 0; c < 4; c++) {
                    ulonglong2 ha = *(const ulonglong2*)&h0d[(4 * kc + c) * 8 + r0];
                    ulonglong2 hb = *(const ulonglong2*)&h0d[(4 * kc + c) * 8 + r0 + 2];
                    hv[c][0] = ha.x; hv[c][1] = ha.y; hv[c][2] = hb.x; hv[c][3] = hb.y;
                }
#pragma unroll
                for (int c = 0; c < 4; c++)
#pragma unroll
                    for (int r = 0; r < 4; r++) {
                        rz[r] = fma2(wrz[c], hv[c][r], rz[r]);
                        iN[r] = fma2(wnd[c], hv[c][r], iN[r]);
                    }
            }
            // B2 section (32 kc)
#pragma unroll
            for (int p = 0; p < 3; p++) {
                unsigned d = b2BufS + p * 1536;
                cpa16(d + 0, gsrcB2rz + p * 256);
                cpa16(d + 512, gsrcB2rz + p * 256 + 128);
                cpa16(d + 1024, gsrcB2n + p * 128);
                CP_COMMIT();
            }
            for (int kc = 0; kc < 32; kc++) {
                if (kc < 30) { CP_WAIT(2); }
                else if (kc == 30) { CP_WAIT(1); }
                else { CP_WAIT(0); }
                const char* bp = b2BufG + (kc % 3) * 1536;
                ulonglong2 w01 = *(const ulonglong2*)(bp + 0);
                ulonglong2 w23 = *(const ulonglong2*)(bp + 512);
                float4 wn4 = *(const float4*)(bp + 1024);
                if (kc + 3 < 32) {
                    unsigned d = b2BufS + ((kc + 3) % 3) * 1536;
                    cpa16(d + 0, gsrcB2rz + (kc + 3) * 256);
                    cpa16(d + 512, gsrcB2rz + (kc + 3) * 256 + 128);
                    cpa16(d + 1024, gsrcB2n + (kc + 3) * 128);
                    CP_COMMIT();
                }
                u64 wrz[4] = {w01.x, w01.y, w23.x, w23.y};
                u64 wnd[4] = {pk2(wn4.x, wn4.x), pk2(wn4.y, wn4.y),
                              pk2(wn4.z, wn4.z), pk2(wn4.w, wn4.w)};
                u64 hv[4][4];
#pragma unroll
                for (int c = 0; c < 4; c++) {
                    ulonglong2 ha = *(const ulonglong2*)&h1d[(4 * kc + c) * 8 + r0];
                    ulonglong2 hb = *(const ulonglong2*)&h1d[(4 * kc + c) * 8 + r0 + 2];
                    hv[c][0] = ha.x; hv[c][1] = ha.y; hv[c][2] = hb.x; hv[c][3] = hb.y;
                }
#pragma unroll
                for (int c = 0; c < 4; c++)
#pragma unroll
                    for (int r = 0; r < 4; r++) {
                        rz[r] = fma2(wrz[c], hv[c][r], rz[r]);
                        hN[r] = fma2(wnd[c], hv[c][r], hN[r]);
                    }
            }
        }
        __syncthreads();
#pragma unroll
        for (int r = 0; r < 4; r++) {
            float ar, az;
            up2(rz[r], ar, az);
            float hold = lo2(h1d[jj * 8 + r0 + r]);
            float rg = sigf(ar), zg = sigf(az);
            float ng = tanh_(lo2(iN[r]) + rg * lo2(hN[r]));
            float v = (1.0f - zg) * ng + zg * hold;
            h1d[jj * 8 + r0 + r] = pk2(v, v);
        }
        __syncthreads();

        // ======== Phase C: layer 2 (direct, as R2) ========
        u64 rz2 = bC_rz, iN2 = bC_in, hN2 = bC_hn;
        for (int kc = 0; kc < 32; kc++) {
            const float4* brz = g_C1rz + kc * 64;
            ulonglong2 w01 = *(const ulonglong2*)(brz + jc);
            ulonglong2 w23 = *(const ulonglong2*)(brz + 32 + jc);
            float4 wn4 = g_C1n[kc * 32 + jc];
            u64 wrz[4] = {w01.x, w01.y, w23.x, w23.y};
            u64 wnd[4] = {pk2(wn4.x, wn4.x), pk2(wn4.y, wn4.y),
                          pk2(wn4.z, wn4.z), pk2(wn4.w, wn4.w)};
#pragma unroll
            for (int c = 0; c < 4; c++) {
                u64 h = h1d[(4 * kc + c) * 8 + rowC];
                rz2 = fma2(wrz[c], h, rz2);
                iN2 = fma2(wnd[c], h, iN2);
            }
        }
        for (int kc = 0; kc < 8; kc++) {
            const float4* brz = g_C2rz + kc * 64;
            ulonglong2 w01 = *(const ulonglong2*)(brz + jc);
            ulonglong2 w23 = *(const ulonglong2*)(brz + 32 + jc);
            float4 wn4 = g_C2n[kc * 32 + jc];
            u64 wrz[4] = {w01.x, w01.y, w23.x, w23.y};
            u64 wnd[4] = {pk2(wn4.x, wn4.x), pk2(wn4.y, wn4.y),
                          pk2(wn4.z, wn4.z), pk2(wn4.w, wn4.w)};
#pragma unroll
            for (int c = 0; c < 4; c++) {
                u64 h = h2d[(4 * kc + c) * 8 + rowC];
                rz2 = fma2(wrz[c], h, rz2);
                hN2 = fma2(wnd[c], h, hN2);
            }
        }
        __syncthreads();
        {
            float cr, cz;
            up2(rz2, cr, cz);
            float hold = lo2(h2d[jc * 8 + rowC]);
            float rg = sigf(cr), zg = sigf(cz);
            float ng = tanh_(lo2(iN2) + rg * lo2(hN2));
            float v = (1.0f - zg) * ng + zg * hold;
            h2d[jc * 8 + rowC] = pk2(v, v);
        }
        __syncthreads();

        // ======== Phase D: projection + argmax ========
        for (int idx = tid; idx < BT * Vsz; idx += NTHR) {
            int row = idx / Vsz, j = idx - row * Vsz;
            float acc = b_proj[j];
#pragma unroll
            for (int k = 0; k < 32; k++)
                acc += g_WprojT[k * Vsz + j] * lo2(h2d[k * 8 + row]);
            out[((size_t)(b0 + row) * Ssz + st) * Vsz + j] = acc;
            lg[row * 44 + j] = acc;
        }
        __syncthreads();
        if (tid < BT && pred) {
            float best = lg[tid * 44];
            int bi = 0;
#pragma unroll 1
            for (int j = 1; j < Vsz; j++) {
                float v = lg[tid * 44 + j];
                if (v > best) { best = v; bi = j; }
            }
            pred[(size_t)(b0 + tid) * Ssz + st] = (float)bi;
        }
        __syncthreads();
    }
}

// ---------------- launch ----------------
extern "C" void kernel_launch(void* const* d_in, const int* in_sizes, int n_in,
                              void* d_out, int out_size) {
    const float* latent  = (const float*)d_in[0];
    const int*   tokens  = (const int*)d_in[1];
    const float* W_emb   = (const float*)d_in[2];
    const float* b_emb   = (const float*)d_in[3];
    const float* W_init  = (const float*)d_in[4];
    const float* b_init  = (const float*)d_in[5];
    const float* Wih0    = (const float*)d_in[6];
    const float* Whh0    = (const float*)d_in[7];
    const float* bih0    = (const float*)d_in[8];
    const float* bhh0    = (const float*)d_in[9];
    const float* Wih1    = (const float*)d_in[10];
    const float* Whh1    = (const float*)d_in[11];
    const float* bih1    = (const float*)d_in[12];
    const float* bhh1    = (const float*)d_in[13];
    const float* Wih2    = (const float*)d_in[14];
    const float* Whh2    = (const float*)d_in[15];
    const float* bih2    = (const float*)d_in[16];
    const float* bhh2    = (const float*)d_in[17];
    const float* W_proj  = (const float*)d_in[18];
    const float* b_proj  = (const float*)d_in[19];

    float* out = (float*)d_out;
    size_t logits_elems = (size_t)Bsz * Ssz * Vsz;
    float* pred = ((size_t)out_size >= logits_elems + (size_t)Bsz * Ssz)
                      ? out + logits_elems : nullptr;

    cudaFuncSetAttribute(k_main, cudaFuncAttributeMaxDynamicSharedMemorySize, SM_TOTAL);

    k_prep<<<256, NTHR>>>(latent, W_emb, b_emb, W_init, b_init, Wih0, bih0, Whh0,
                          Wih1, Whh1, Wih2, Whh2, W_proj);
    k_main<<<NCTA, NTHR, SM_TOTAL>>>(tokens, bhh0, bih1, bhh1, bih2, bhh2, b_proj, out, pred);
}

// round 12
// speedup vs baseline: 1.6067x; 1.6067x over previous
#include <cuda_runtime.h>
#include <math.h>

#define Bsz 1024
#define Ssz 350
#define Vsz 41
#define BT 8
#define NCTA 128
#define NTHR 256

typedef unsigned long long u64;

// ---------------- persistent device scratch ----------------
__device__ float4 g_wA[49152];     // Whh0: [kc][gate][256] -> W[g*256+t][4kc..4kc+3]
__device__ float4 g_wB1[24576];    // Wih1: [kc][gate][128]
__device__ float4 g_wB2[12288];    // Whh1: [kc][gate][128]
__device__ float4 g_wC1[3072];     // Wih2: [kc][gate][32]
__device__ float4 g_wC2[768];      // Whh2: [kc][gate][32]
__device__ float  g_WprojT[1312];  // [k][j]
__device__ float  g_G0[41 * 768];  // [v][col] = bih0 + Wih0 @ emb[v]
__device__ float  g_Hinit[Bsz * 416];

// ---------------- f32x2 helpers ----------------
__device__ __forceinline__ u64 fma2(u64 a, u64 b, u64 c) {
    u64 d; asm("fma.rn.f32x2 %0,%1,%2,%3;" : "=l"(d) : "l"(a), "l"(b), "l"(c)); return d;
}
__device__ __forceinline__ u64 pk2(float x, float y) {
    u64 d; asm("mov.b64 %0,{%1,%2};" : "=l"(d) : "f"(x), "f"(y)); return d;
}
__device__ __forceinline__ void up2(u64 a, float& x, float& y) {
    asm("mov.b64 {%0,%1}, %2;" : "=f"(x), "=f"(y) : "l"(a));
}
__device__ __forceinline__ float sigf(float x) {
    return __fdividef(1.0f, 1.0f + __expf(-x));
}
__device__ __forceinline__ float tanh_(float x) {
    float ax = fabsf(x);
    float e = __expf(-2.0f * ax);
    float t = __fdividef(1.0f - e, 1.0f + e);
    return copysignf(t, x);
}

// ---------------- fused prep kernel ----------------
// blocks 0..127: Hinit; 128..168: G0; 169..255: weight packing + WprojT
__global__ void k_prep(const float* __restrict__ latent, const float* __restrict__ W_emb,
                       const float* __restrict__ b_emb, const float* __restrict__ W_init,
                       const float* __restrict__ b_init, const float* __restrict__ Wih0,
                       const float* __restrict__ bih0, const float* __restrict__ Whh0,
                       const float* __restrict__ Wih1, const float* __restrict__ Whh1,
                       const float* __restrict__ Wih2, const float* __restrict__ Whh2,
                       const float* __restrict__ W_proj) {
    const int b = blockIdx.x, tid = threadIdx.x;
    if (b < 128) {
        __shared__ float lat[8 * 512];
        const int b0 = b * 8;
        for (int i = tid; i < 8 * 512; i += NTHR) lat[i] = latent[(size_t)b0 * 512 + i];
        __syncthreads();
        for (int c = tid; c < 416; c += NTHR) {
            float acc[8];
            float bi = b_init[c];
#pragma unroll
            for (int r = 0; r < 8; r++) acc[r] = bi;
            const float* w = W_init + (size_t)c * 512;
            for (int k = 0; k < 512; k += 4) {
                float4 wv = *(const float4*)(w + k);
#pragma unroll
                for (int r = 0; r < 8; r++) {
                    acc[r] += wv.x * lat[r * 512 + k];
                    acc[r] += wv.y * lat[r * 512 + k + 1];
                    acc[r] += wv.z * lat[r * 512 + k + 2];
                    acc[r] += wv.w * lat[r * 512 + k + 3];
                }
            }
#pragma unroll
            for (int r = 0; r < 8; r++) g_Hinit[(size_t)(b0 + r) * 416 + c] = acc[r];
        }
    } else if (b < 169) {
        const int v = b - 128;
        __shared__ float emb[512];
        for (int k = tid; k < 512; k += NTHR) emb[k] = W_emb[k * Vsz + v] + b_emb[k];
        __syncthreads();
        for (int j = tid; j < 768; j += NTHR) {
            float acc = bih0[j];
            const float* w = Wih0 + (size_t)j * 512;
            for (int k = 0; k < 512; k += 4) {
                float4 wv = *(const float4*)(w + k);
                acc += wv.x * emb[k] + wv.y * emb[k + 1] + wv.z * emb[k + 2] + wv.w * emb[k + 3];
            }
            g_G0[v * 768 + j] = acc;
        }
    } else {
        const int TOTAL = 90184;
        for (int i = (b - 169) * NTHR + tid; i < TOTAL; i += 87 * NTHR) {
            if (i < 49152) {             // wA: [kc][g][256]
                int kc = i / 768, rem = i % 768;
                int row = rem;           // g*256 + t
                g_wA[i] = *(const float4*)&Whh0[(size_t)row * 256 + 4 * kc];
            } else if (i < 73728) {      // wB1: [kc][g][128]
                int t = i - 49152;
                int kc = t / 384, row = t % 384;
                g_wB1[t] = *(const float4*)&Wih1[(size_t)row * 256 + 4 * kc];
            } else if (i < 86016) {      // wB2
                int t = i - 73728;
                int kc = t / 384, row = t % 384;
                g_wB2[t] = *(const float4*)&Whh1[(size_t)row * 128 + 4 * kc];
            } else if (i < 89088) {      // wC1
                int t = i - 86016;
                int kc = t / 96, row = t % 96;
                g_wC1[t] = *(const float4*)&Wih2[(size_t)row * 128 + 4 * kc];
            } else if (i < 89856) {      // wC2
                int t = i - 89088;
                int kc = t / 96, row = t % 96;
                g_wC2[t] = *(const float4*)&Whh2[(size_t)row * 32 + 4 * kc];
            } else {                     // WprojT
                int t2 = i - 89856;
#pragma unroll
                for (int c = 0; c < 4; c++) {
                    int e = t2 * 4 + c;
                    if (e < 1312) {
                        int k = e / Vsz, j = e - k * Vsz;
                        g_WprojT[e] = W_proj[j * 32 + k];
                    }
                }
            }
        }
    }
}

// ---------------- main persistent GRU kernel (column-owner, row-pair f32x2) ----------------
__global__ __launch_bounds__(NTHR, 1)
void k_main(const int* __restrict__ tokens,
            const float* __restrict__ bhh0,
            const float* __restrict__ bih1, const float* __restrict__ bhh1,
            const float* __restrict__ bih2, const float* __restrict__ bhh2,
            const float* __restrict__ b_proj,
            float* __restrict__ out, float* __restrict__ pred) {
    // h layouts: [k][rp] row-pairs, u64 = (h[k][2rp], h[k][2rp+1])
    __shared__ __align__(16) u64 hrp0[256 * 4];
    __shared__ __align__(16) u64 hrp1[128 * 4];
    __shared__ __align__(16) u64 hrp2[32 * 4];
    __shared__ float lg[BT][44];
    __shared__ int toksAll[Ssz * 8];

    const int tid = threadIdx.x;
    const int b0 = blockIdx.x * BT;
    const int jj = tid & 127;          // phase B column
    const int rh = tid >> 7;           // phase B row-half (rp base 2*rh)
    const int rpb = 2 * rh;
    const int jc = tid & 31;           // phase C column
    const int qC = tid >> 5;           // phase C rp (valid when tid<128)

    // tokens preload (SOS at step 0)
    for (int i = tid; i < Ssz * 8; i += NTHR) {
        int stt = i >> 3, row = i & 7;
        toksAll[i] = (stt == 0) ? 1 : tokens[(size_t)(b0 + row) * Ssz + stt];
    }

    // initial state -> row-pair smem ([k][rp] float view = [k*8 + row])
    for (int idx = tid; idx < BT * 416; idx += NTHR) {
        int row = idx / 416, c = idx - row * 416;
        float v = g_Hinit[(size_t)(b0 + row) * 416 + c];
        if (c < 256)      ((float*)hrp0)[c * 8 + row] = v;
        else if (c < 384) ((float*)hrp1)[(c - 256) * 8 + row] = v;
        else              ((float*)hrp2)[(c - 384) * 8 + row] = v;
    }

    // biases
    const float bR0 = bhh0[tid], bZ0 = bhh0[256 + tid], bN0 = bhh0[512 + tid];
    const u64 bN0d = pk2(bN0, bN0);
    const u64 bBr = pk2(bih1[jj] + bhh1[jj], bih1[jj] + bhh1[jj]);
    const u64 bBz = pk2(bih1[128 + jj] + bhh1[128 + jj], bih1[128 + jj] + bhh1[128 + jj]);
    const u64 bBi = pk2(bih1[256 + jj], bih1[256 + jj]);
    const u64 bBh = pk2(bhh1[256 + jj], bhh1[256 + jj]);
    const u64 bCr = pk2(bih2[jc] + bhh2[jc], bih2[jc] + bhh2[jc]);
    const u64 bCz = pk2(bih2[32 + jc] + bhh2[32 + jc], bih2[32 + jc] + bhh2[32 + jc]);
    const u64 bCi = pk2(bih2[64 + jc], bih2[64 + jc]);
    const u64 bCh = pk2(bhh2[64 + jc], bhh2[64 + jc]);

    const float4* wAp = g_wA + tid;     // [kc][g][256]
    const float4* wB1p = g_wB1 + jj;    // [kc][g][128]
    const float4* wB2p = g_wB2 + jj;
    const float4* wC1p = g_wC1 + jc;    // [kc][g][32]
    const float4* wC2p = g_wC2 + jc;

    __syncthreads();

    for (int st = 0; st < Ssz; st++) {
        const int* tokrow = toksAll + st * 8;

        // ======== Phase A: layer 0 — thread owns all gates of col tid, 8 rows ========
        {
            u64 aR[4], aZ[4], aN[4];
#pragma unroll
            for (int rp = 0; rp < 4; rp++) {
                const float* ge = g_G0 + (size_t)tokrow[2 * rp] * 768;
                const float* go = g_G0 + (size_t)tokrow[2 * rp + 1] * 768;
                aR[rp] = pk2(ge[tid] + bR0, go[tid] + bR0);
                aZ[rp] = pk2(ge[256 + tid] + bZ0, go[256 + tid] + bZ0);
                aN[rp] = bN0d;
            }
            for (int kc = 0; kc < 64; kc++) {
                float4 wr = wAp[kc * 768];
                float4 wz = wAp[kc * 768 + 256];
                float4 wn = wAp[kc * 768 + 512];
                const float wrr[4] = {wr.x, wr.y, wr.z, wr.w};
                const float wzz[4] = {wz.x, wz.y, wz.z, wz.w};
                const float wnn[4] = {wn.x, wn.y, wn.z, wn.w};
#pragma unroll
                for (int c = 0; c < 4; c++) {
                    int k = 4 * kc + c;
                    ulonglong2 hA = *(const ulonglong2*)&hrp0[k * 4];
                    ulonglong2 hB = *(const ulonglong2*)&hrp0[k * 4 + 2];
                    u64 wrd = pk2(wrr[c], wrr[c]);
                    u64 wzd = pk2(wzz[c], wzz[c]);
                    u64 wnd = pk2(wnn[c], wnn[c]);
                    aR[0] = fma2(wrd, hA.x, aR[0]); aR[1] = fma2(wrd, hA.y, aR[1]);
                    aR[2] = fma2(wrd, hB.x, aR[2]); aR[3] = fma2(wrd, hB.y, aR[3]);
                    aZ[0] = fma2(wzd, hA.x, aZ[0]); aZ[1] = fma2(wzd, hA.y, aZ[1]);
                    aZ[2] = fma2(wzd, hB.x, aZ[2]); aZ[3] = fma2(wzd, hB.y, aZ[3]);
                    aN[0] = fma2(wnd, hA.x, aN[0]); aN[1] = fma2(wnd, hA.y, aN[1]);
                    aN[2] = fma2(wnd, hB.x, aN[2]); aN[3] = fma2(wnd, hB.y, aN[3]);
                }
            }
            __syncthreads();
#pragma unroll
            for (int rp = 0; rp < 4; rp++) {
                float r0e, r1e, z0e, z1e, n0e, n1e, h0e, h1e;
                up2(aR[rp], r0e, r1e); up2(aZ[rp], z0e, z1e); up2(aN[rp], n0e, n1e);
                float gi0 = g_G0[(size_t)tokrow[2 * rp] * 768 + 512 + tid];
                float gi1 = g_G0[(size_t)tokrow[2 * rp + 1] * 768 + 512 + tid];
                up2(hrp0[tid * 4 + rp], h0e, h1e);
                float rg0 = sigf(r0e), rg1 = sigf(r1e);
                float zg0 = sigf(z0e), zg1 = sigf(z1e);
                float ng0 = tanh_(gi0 + rg0 * n0e), ng1 = tanh_(gi1 + rg1 * n1e);
                float v0 = (1.0f - zg0) * ng0 + zg0 * h0e;
                float v1 = (1.0f - zg1) * ng1 + zg1 * h1e;
                hrp0[tid * 4 + rp] = pk2(v0, v1);
            }
            __syncthreads();
        }

        // ======== Phase B: layer 1 — thread (jj, rh): all gates of col jj, 4 rows ========
        {
            u64 rB[2], zB[2], iB[2], hB[2];
#pragma unroll
            for (int i = 0; i < 2; i++) { rB[i] = bBr; zB[i] = bBz; iB[i] = bBi; hB[i] = bBh; }
            for (int kc = 0; kc < 64; kc++) {
                float4 wr = wB1p[kc * 384];
                float4 wz = wB1p[kc * 384 + 128];
                float4 wn = wB1p[kc * 384 + 256];
                const float wrr[4] = {wr.x, wr.y, wr.z, wr.w};
                const float wzz[4] = {wz.x, wz.y, wz.z, wz.w};
                const float wnn[4] = {wn.x, wn.y, wn.z, wn.w};
#pragma unroll
                for (int c = 0; c < 4; c++) {
                    int k = 4 * kc + c;
                    ulonglong2 h = *(const ulonglong2*)&hrp0[k * 4 + rpb];
                    u64 wrd = pk2(wrr[c], wrr[c]);
                    u64 wzd = pk2(wzz[c], wzz[c]);
                    u64 wnd = pk2(wnn[c], wnn[c]);
                    rB[0] = fma2(wrd, h.x, rB[0]); rB[1] = fma2(wrd, h.y, rB[1]);
                    zB[0] = fma2(wzd, h.x, zB[0]); zB[1] = fma2(wzd, h.y, zB[1]);
                    iB[0] = fma2(wnd, h.x, iB[0]); iB[1] = fma2(wnd, h.y, iB[1]);
                }
            }
            for (int kc = 0; kc < 32; kc++) {
                float4 wr = wB2p[kc * 384];
                float4 wz = wB2p[kc * 384 + 128];
                float4 wn = wB2p[kc * 384 + 256];
                const float wrr[4] = {wr.x, wr.y, wr.z, wr.w};
                const float wzz[4] = {wz.x, wz.y, wz.z, wz.w};
                const float wnn[4] = {wn.x, wn.y, wn.z, wn.w};
#pragma unroll
                for (int c = 0; c < 4; c++) {
                    int k = 4 * kc + c;
                    ulonglong2 h = *(const ulonglong2*)&hrp1[k * 4 + rpb];
                    u64 wrd = pk2(wrr[c], wrr[c]);
                    u64 wzd = pk2(wzz[c], wzz[c]);
                    u64 wnd = pk2(wnn[c], wnn[c]);
                    rB[0] = fma2(wrd, h.x, rB[0]); rB[1] = fma2(wrd, h.y, rB[1]);
                    zB[0] = fma2(wzd, h.x, zB[0]); zB[1] = fma2(wzd, h.y, zB[1]);
                    hB[0] = fma2(wnd, h.x, hB[0]); hB[1] = fma2(wnd, h.y, hB[1]);
                }
            }
            __syncthreads();
#pragma unroll
            for (int i = 0; i < 2; i++) {
                float r0e, r1e, z0e, z1e, i0e, i1e, n0e, n1e, h0e, h1e;
                up2(rB[i], r0e, r1e); up2(zB[i], z0e, z1e);
                up2(iB[i], i0e, i1e); up2(hB[i], n0e, n1e);
                up2(hrp1[jj * 4 + rpb + i], h0e, h1e);
                float rg0 = sigf(r0e), rg1 = sigf(r1e);
                float zg0 = sigf(z0e), zg1 = sigf(z1e);
                float ng0 = tanh_(i0e + rg0 * n0e), ng1 = tanh_(i1e + rg1 * n1e);
                float v0 = (1.0f - zg0) * ng0 + zg0 * h0e;
                float v1 = (1.0f - zg1) * ng1 + zg1 * h1e;
                hrp1[jj * 4 + rpb + i] = pk2(v0, v1);
            }
            __syncthreads();
        }

        // ======== Phase C: layer 2 — threads 0..127: (jc, qC): all gates, 2 rows ========
        if (tid < 128) {
            u64 rC = bCr, zC = bCz, iC = bCi, hC = bCh;
            for (int kc = 0; kc < 32; kc++) {
                float4 wr = wC1p[kc * 96];
                float4 wz = wC1p[kc * 96 + 32];
                float4 wn = wC1p[kc * 96 + 64];
                const float wrr[4] = {wr.x, wr.y, wr.z, wr.w};
                const float wzz[4] = {wz.x, wz.y, wz.z, wz.w};
                const float wnn[4] = {wn.x, wn.y, wn.z, wn.w};
#pragma unroll
                for (int c = 0; c < 4; c++) {
                    u64 h = hrp1[(4 * kc + c) * 4 + qC];
                    rC = fma2(pk2(wrr[c], wrr[c]), h, rC);
                    zC = fma2(pk2(wzz[c], wzz[c]), h, zC);
                    iC = fma2(pk2(wnn[c], wnn[c]), h, iC);
                }
            }
            for (int kc = 0; kc < 8; kc++) {
                float4 wr = wC2p[kc * 96];
                float4 wz = wC2p[kc * 96 + 32];
                float4 wn = wC2p[kc * 96 + 64];
                const float wrr[4] = {wr.x, wr.y, wr.z, wr.w};
                const float wzz[4] = {wz.x, wz.y, wz.z, wz.w};
                const float wnn[4] = {wn.x, wn.y, wn.z, wn.w};
#pragma unroll
                for (int c = 0; c < 4; c++) {
                    u64 h = hrp2[(4 * kc + c) * 4 + qC];
                    rC = fma2(pk2(wrr[c], wrr[c]), h, rC);
                    zC = fma2(pk2(wzz[c], wzz[c]), h, zC);
                    hC = fma2(pk2(wnn[c], wnn[c]), h, hC);
                }
            }
            __syncthreads();
            {
                float r0e, r1e, z0e, z1e, i0e, i1e, n0e, n1e, h0e, h1e;
                up2(rC, r0e, r1e); up2(zC, z0e, z1e);
                up2(iC, i0e, i1e); up2(hC, n0e, n1e);
                up2(hrp2[jc * 4 + qC], h0e, h1e);
                float rg0 = sigf(r0e), rg1 = sigf(r1e);
                float zg0 = sigf(z0e), zg1 = sigf(z1e);
                float ng0 = tanh_(i0e + rg0 * n0e), ng1 = tanh_(i1e + rg1 * n1e);
                float v0 = (1.0f - zg0) * ng0 + zg0 * h0e;
                float v1 = (1.0f - zg1) * ng1 + zg1 * h1e;
                hrp2[jc * 4 + qC] = pk2(v0, v1);
            }
        } else {
            __syncthreads();
        }
        __syncthreads();

        // ======== Phase D: projection + argmax ========
        {
            const float* h2f = (const float*)hrp2;   // [k*8 + row]
            for (int idx = tid; idx < BT * Vsz; idx += NTHR) {
                int row = idx / Vsz, j = idx - row * Vsz;
                float acc = b_proj[j];
#pragma unroll
                for (int k = 0; k < 32; k++)
                    acc += g_WprojT[k * Vsz + j] * h2f[k * 8 + row];
                out[((size_t)(b0 + row) * Ssz + st) * Vsz + j] = acc;
                lg[row][j] = acc;
            }
        }
        __syncthreads();
        if (tid < BT && pred) {
            float best = lg[tid][0];
            int bi = 0;
#pragma unroll 1
            for (int j = 1; j < Vsz; j++) {
                float v = lg[tid][j];
                if (v > best) { best = v; bi = j; }
            }
            pred[(size_t)(b0 + tid) * Ssz + st] = (float)bi;
        }
        __syncthreads();
    }
}

// ---------------- launch ----------------
extern "C" void kernel_launch(void* const* d_in, const int* in_sizes, int n_in,
                              void* d_out, int out_size) {
    const float* latent  = (const float*)d_in[0];
    const int*   tokens  = (const int*)d_in[1];
    const float* W_emb   = (const float*)d_in[2];
    const float* b_emb   = (const float*)d_in[3];
    const float* W_init  = (const float*)d_in[4];
    const float* b_init  = (const float*)d_in[5];
    const float* Wih0    = (const float*)d_in[6];
    const float* Whh0    = (const float*)d_in[7];
    const float* bih0    = (const float*)d_in[8];
    const float* bhh0    = (const float*)d_in[9];
    const float* Wih1    = (const float*)d_in[10];
    const float* Whh1    = (const float*)d_in[11];
    const float* bih1    = (const float*)d_in[12];
    const float* bhh1    = (const float*)d_in[13];
    const float* Wih2    = (const float*)d_in[14];
    const float* Whh2    = (const float*)d_in[15];
    const float* bih2    = (const float*)d_in[16];
    const float* bhh2    = (const float*)d_in[17];
    const float* W_proj  = (const float*)d_in[18];
    const float* b_proj  = (const float*)d_in[19];

    float* out = (float*)d_out;
    size_t logits_elems = (size_t)Bsz * Ssz * Vsz;
    float* pred = ((size_t)out_size >= logits_elems + (size_t)Bsz * Ssz)
                      ? out + logits_elems : nullptr;

    k_prep<<<256, NTHR>>>(latent, W_emb, b_emb, W_init, b_init, Wih0, bih0, Whh0,
                          Wih1, Whh1, Wih2, Whh2, W_proj);
    k_main<<<NCTA, NTHR>>>(tokens, bhh0, bih1, bhh1, bih2, bhh2, b_proj, out, pred);
}